// round 14
// baseline (speedup 1.0000x reference)
#include <cuda_runtime.h>
#include <cuda_bf16.h>
#include <math.h>
#include <stdint.h>

#define HIDDEN 2048
#define HEADS 16
#define HEAD_DIM 128
#define BATCH 2
#define SEQ 2048
#define MTOT (BATCH * SEQ)     // 4096
#define BH (BATCH * HEADS)     // 32
#define WROW (HIDDEN / 2)      // 1024 bf16x2 words per row

// ---------------- scratch (device globals; no allocations allowed) ----------
__device__ float g_q[MTOT * HIDDEN];
__device__ float g_k[MTOT * HIDDEN];
__device__ float g_v[MTOT * HIDDEN];
__device__ float g_sc[(size_t)BH * SEQ * SEQ];          // 512 MiB float scores

// pre-split bf16x2 word streams (hi+lo = same bytes as the float original)
__device__ uint32_t g_xh[MTOT * WROW], g_xl[MTOT * WROW];
__device__ uint32_t g_wh[4][HIDDEN * WROW], g_wl[4][HIDDEN * WROW];
__device__ uint32_t g_qh[MTOT * WROW], g_ql[MTOT * WROW];
__device__ uint32_t g_kh[MTOT * WROW], g_kl[MTOT * WROW];
__device__ uint32_t g_ph[(size_t)BH * SEQ * (SEQ / 2)];
__device__ uint32_t g_pl[(size_t)BH * SEQ * (SEQ / 2)];
__device__ uint32_t g_ch[MTOT * WROW], g_cl[MTOT * WROW];

// ---------------------------------------------------------------------------
__device__ __forceinline__ void pack_split(float v0, float v1,
                                           uint32_t& hi, uint32_t& lo) {
    __nv_bfloat162 h = __floats2bfloat162_rn(v0, v1);
    float2 hf = __bfloat1622float2(h);
    __nv_bfloat162 l = __floats2bfloat162_rn(v0 - hf.x, v1 - hf.y);
    hi = *reinterpret_cast<uint32_t*>(&h);
    lo = *reinterpret_cast<uint32_t*>(&l);
}

__device__ __forceinline__ void mma_bf16(float* c, const uint32_t* a, const uint32_t* b) {
    asm("mma.sync.aligned.m16n8k16.row.col.f32.bf16.bf16.f32 "
        "{%0,%1,%2,%3}, {%4,%5,%6,%7}, {%8,%9}, {%0,%1,%2,%3};"
        : "+f"(c[0]), "+f"(c[1]), "+f"(c[2]), "+f"(c[3])
        : "r"(a[0]), "r"(a[1]), "r"(a[2]), "r"(a[3]), "r"(b[0]), "r"(b[1]));
}

#define S2 20
#define TILE2 (128 * S2)
#define SMEM2 (4 * TILE2 * 4)    // 40960 B

// one 16-word (32-k) chunk of 3xBF16 mma (proven core, unchanged from R11)
__device__ __forceinline__ void mma_chunk2(
    const uint32_t* Ah, const uint32_t* Al, const uint32_t* Bh, const uint32_t* Bl,
    int wm, int wn, int gid, int tq, float acc[4][4][4]) {
#pragma unroll
    for (int ks = 0; ks < 2; ks++) {
        const int kb = ks * 8;
        uint32_t bh[4][2], bl[4][2];
#pragma unroll
        for (int nt = 0; nt < 4; nt++) {
            int nr = (wn + nt * 8 + gid) * S2 + kb + tq;
            bh[nt][0] = Bh[nr];
            bh[nt][1] = Bh[nr + 4];
            bl[nt][0] = Bl[nr];
            bl[nt][1] = Bl[nr + 4];
        }
        uint32_t af[4][4];
#pragma unroll
        for (int mt = 0; mt < 4; mt++) {
            int r = (wm + mt * 16 + gid) * S2 + kb + tq;
            af[mt][0] = Ah[r];
            af[mt][1] = Ah[r + 8 * S2];
            af[mt][2] = Ah[r + 4];
            af[mt][3] = Ah[r + 8 * S2 + 4];
        }
#pragma unroll
        for (int mt = 0; mt < 4; mt++)
#pragma unroll
            for (int nt = 0; nt < 4; nt++) {
                mma_bf16(acc[mt][nt], af[mt], bh[nt]);
                mma_bf16(acc[mt][nt], af[mt], bl[nt]);
            }
#pragma unroll
        for (int mt = 0; mt < 4; mt++) {
            int r = (wm + mt * 16 + gid) * S2 + kb + tq;
            af[mt][0] = Al[r];
            af[mt][1] = Al[r + 8 * S2];
            af[mt][2] = Al[r + 4];
            af[mt][3] = Al[r + 8 * S2 + 4];
        }
#pragma unroll
        for (int mt = 0; mt < 4; mt++)
#pragma unroll
            for (int nt = 0; nt < 4; nt++)
                mma_bf16(acc[mt][nt], af[mt], bh[nt]);
    }
}

// store 8 contiguous words to smem (8B-aligned; S2=20 rows)
__device__ __forceinline__ void sts8(uint32_t* d, uint4 a, uint4 b) {
    *(uint2*)(d + 0) = make_uint2(a.x, a.y);
    *(uint2*)(d + 2) = make_uint2(a.z, a.w);
    *(uint2*)(d + 4) = make_uint2(b.x, b.y);
    *(uint2*)(d + 6) = make_uint2(b.z, b.w);
}

// ---------------------------------------------------------------------------
// split_pair: float array -> (hi, lo) bf16x2 word arrays. 4 words/thread.
// ---------------------------------------------------------------------------
__global__ void split_pair(const float* __restrict__ in,
                           uint32_t* __restrict__ hi, uint32_t* __restrict__ lo,
                           int nwords4) {
    int i = blockIdx.x * blockDim.x + threadIdx.x;
    if (i >= nwords4) return;
    float4 f0 = ((const float4*)in)[2 * i];
    float4 f1 = ((const float4*)in)[2 * i + 1];
    uint4 h, l;
    pack_split(f0.x, f0.y, h.x, l.x);
    pack_split(f0.z, f0.w, h.y, l.y);
    pack_split(f1.x, f1.y, h.z, l.z);
    pack_split(f1.z, f1.w, h.w, l.w);
    ((uint4*)hi)[i] = h;
    ((uint4*)lo)[i] = l;
}

// ---------------------------------------------------------------------------
// Pre-split NT GEMM: C = A*B^T from word streams. Pure-copy staging.
// ---------------------------------------------------------------------------
__global__ __launch_bounds__(256, 2)
void gemm_ps(const uint32_t* __restrict__ Ahg, const uint32_t* __restrict__ Alg,
             const uint32_t* __restrict__ Bhg, const uint32_t* __restrict__ Blg,
             float* __restrict__ C) {
    extern __shared__ __align__(16) uint32_t sm[];
    uint32_t* Ah = sm;
    uint32_t* Al = Ah + TILE2;
    uint32_t* Bh = Al + TILE2;
    uint32_t* Bl = Bh + TILE2;

    const int tid = threadIdx.x;
    const int warp = tid >> 5, lane = tid & 31;
    const int gid = lane >> 2, tq = lane & 3;
    const int wm = (warp & 1) * 64;
    const int wn = (warp >> 1) * 32;
    const int m0 = blockIdx.y * 128, n0 = blockIdx.x * 128;
    const int lr = tid >> 1, wb = (tid & 1) * 8;

    float acc[4][4][4];
#pragma unroll
    for (int mt = 0; mt < 4; mt++)
#pragma unroll
        for (int nt = 0; nt < 4; nt++)
#pragma unroll
            for (int r = 0; r < 4; r++) acc[mt][nt][r] = 0.f;

    const size_t arow = (size_t)(m0 + lr) * WROW + wb;
    const size_t brow = (size_t)(n0 + lr) * WROW + wb;

    for (int kt2 = 0; kt2 < WROW; kt2 += 16) {
        uint4 a0 = *(const uint4*)(Ahg + arow + kt2);
        uint4 a1 = *(const uint4*)(Ahg + arow + kt2 + 4);
        uint4 b0 = *(const uint4*)(Alg + arow + kt2);
        uint4 b1 = *(const uint4*)(Alg + arow + kt2 + 4);
        uint4 c0 = *(const uint4*)(Bhg + brow + kt2);
        uint4 c1 = *(const uint4*)(Bhg + brow + kt2 + 4);
        uint4 d0 = *(const uint4*)(Blg + brow + kt2);
        uint4 d1 = *(const uint4*)(Blg + brow + kt2 + 4);
        __syncthreads();
        const int off = lr * S2 + wb;
        sts8(&Ah[off], a0, a1);
        sts8(&Al[off], b0, b1);
        sts8(&Bh[off], c0, c1);
        sts8(&Bl[off], d0, d1);
        __syncthreads();
        mma_chunk2(Ah, Al, Bh, Bl, wm, wn, gid, tq, acc);
    }

#pragma unroll
    for (int mt = 0; mt < 4; mt++) {
        int row = m0 + wm + mt * 16 + gid;
#pragma unroll
        for (int nt = 0; nt < 4; nt++) {
            int col = n0 + wn + nt * 8 + 2 * tq;
            *(float2*)&C[(size_t)row * HIDDEN + col] =
                make_float2(acc[mt][nt][0], acc[mt][nt][1]);
            *(float2*)&C[(size_t)(row + 8) * HIDDEN + col] =
                make_float2(acc[mt][nt][2], acc[mt][nt][3]);
        }
    }
}

// ---------------------------------------------------------------------------
// Scores from pre-split q/k words: S = (Q.K^T)*scale, lower-triangle blocks.
// ---------------------------------------------------------------------------
__global__ __launch_bounds__(256, 2)
void scores_ps() {
    const int k0 = blockIdx.x * 128;
    const int q0 = blockIdx.y * 128;
    if (k0 > q0) return;
    const int bh = blockIdx.z;
    const int b = bh >> 4, h = bh & 15;

    extern __shared__ __align__(16) uint32_t sm[];
    uint32_t* Ah = sm;
    uint32_t* Al = Ah + TILE2;
    uint32_t* Bh = Al + TILE2;
    uint32_t* Bl = Bh + TILE2;

    const int tid = threadIdx.x;
    const int warp = tid >> 5, lane = tid & 31;
    const int gid = lane >> 2, tq = lane & 3;
    const int wm = (warp & 1) * 64;
    const int wn = (warp >> 1) * 32;
    const int lr = tid >> 1, wb = (tid & 1) * 8;

    float* S = g_sc + (size_t)bh * SEQ * SEQ;
    const size_t qrow = ((size_t)b * SEQ + q0 + lr) * WROW + h * 64 + wb;
    const size_t krow = ((size_t)b * SEQ + k0 + lr) * WROW + h * 64 + wb;

    float acc[4][4][4];
#pragma unroll
    for (int mt = 0; mt < 4; mt++)
#pragma unroll
        for (int nt = 0; nt < 4; nt++)
#pragma unroll
            for (int r = 0; r < 4; r++) acc[mt][nt][r] = 0.f;

#pragma unroll
    for (int kt2 = 0; kt2 < 64; kt2 += 16) {
        uint4 a0 = *(const uint4*)(g_qh + qrow + kt2);
        uint4 a1 = *(const uint4*)(g_qh + qrow + kt2 + 4);
        uint4 b0 = *(const uint4*)(g_ql + qrow + kt2);
        uint4 b1 = *(const uint4*)(g_ql + qrow + kt2 + 4);
        uint4 c0 = *(const uint4*)(g_kh + krow + kt2);
        uint4 c1 = *(const uint4*)(g_kh + krow + kt2 + 4);
        uint4 d0 = *(const uint4*)(g_kl + krow + kt2);
        uint4 d1 = *(const uint4*)(g_kl + krow + kt2 + 4);
        __syncthreads();
        const int off = lr * S2 + wb;
        sts8(&Ah[off], a0, a1);
        sts8(&Al[off], b0, b1);
        sts8(&Bh[off], c0, c1);
        sts8(&Bl[off], d0, d1);
        __syncthreads();
        mma_chunk2(Ah, Al, Bh, Bl, wm, wn, gid, tq, acc);
    }

    const float scale = 0.08838834764831845f;
#pragma unroll
    for (int mt = 0; mt < 4; mt++) {
        int row = q0 + wm + mt * 16 + gid;
#pragma unroll
        for (int nt = 0; nt < 4; nt++) {
            int col = k0 + wn + nt * 8 + 2 * tq;
            *(float2*)&S[(size_t)row * SEQ + col] =
                make_float2(acc[mt][nt][0] * scale, acc[mt][nt][1] * scale);
            *(float2*)&S[(size_t)(row + 8) * SEQ + col] =
                make_float2(acc[mt][nt][2] * scale, acc[mt][nt][3] * scale);
        }
    }
}

// ---------------------------------------------------------------------------
// PV: ctx = P*V. P from pre-split words (pure copy); V transpose-split
// in-kernel (unchanged); epilogue writes split ctx words directly.
// ---------------------------------------------------------------------------
__global__ __launch_bounds__(256, 2)
void pv_ps() {
    const int q0 = blockIdx.x * 128;
    const int bh = blockIdx.y;
    const int b = bh >> 4, h = bh & 15;

    extern __shared__ __align__(16) uint32_t sm[];
    uint32_t* Ah = sm;
    uint32_t* Al = Ah + TILE2;
    uint32_t* Bh = Al + TILE2;
    uint32_t* Bl = Bh + TILE2;

    const int tid = threadIdx.x;
    const int warp = tid >> 5, lane = tid & 31;
    const int gid = lane >> 2, tq = lane & 3;
    const int wm = (warp & 1) * 64;
    const int wn = (warp >> 1) * 32;
    const int lr = tid >> 1, wb = (tid & 1) * 8;
    const int vp = tid & 15;
    const int vd = (tid >> 4) * 8;

    const size_t prow = (size_t)bh * SEQ * (SEQ / 2)
                      + (size_t)(q0 + lr) * (SEQ / 2) + wb;
    const float* V = g_v + (size_t)b * SEQ * HIDDEN + h * HEAD_DIM;

    float acc[4][4][4];
#pragma unroll
    for (int mt = 0; mt < 4; mt++)
#pragma unroll
        for (int nt = 0; nt < 4; nt++)
#pragma unroll
            for (int r = 0; r < 4; r++) acc[mt][nt][r] = 0.f;

    const int kmax2 = (q0 + 128) / 2;
    for (int kt2 = 0; kt2 < kmax2; kt2 += 16) {
        uint4 a0 = *(const uint4*)(g_ph + prow + kt2);
        uint4 a1 = *(const uint4*)(g_ph + prow + kt2 + 4);
        uint4 b0 = *(const uint4*)(g_pl + prow + kt2);
        uint4 b1 = *(const uint4*)(g_pl + prow + kt2 + 4);
        const int kt = kt2 * 2;
        float4 v0a = *(const float4*)&V[(size_t)(kt + 2 * vp) * HIDDEN + vd];
        float4 v0b = *(const float4*)&V[(size_t)(kt + 2 * vp) * HIDDEN + vd + 4];
        float4 v1a = *(const float4*)&V[(size_t)(kt + 2 * vp + 1) * HIDDEN + vd];
        float4 v1b = *(const float4*)&V[(size_t)(kt + 2 * vp + 1) * HIDDEN + vd + 4];
        __syncthreads();
        const int off = lr * S2 + wb;
        sts8(&Ah[off], a0, a1);
        sts8(&Al[off], b0, b1);
        {
            float r0[8] = {v0a.x, v0a.y, v0a.z, v0a.w, v0b.x, v0b.y, v0b.z, v0b.w};
            float r1[8] = {v1a.x, v1a.y, v1a.z, v1a.w, v1b.x, v1b.y, v1b.z, v1b.w};
#pragma unroll
            for (int j = 0; j < 8; j++) {
                uint32_t hw, lw;
                pack_split(r0[j], r1[j], hw, lw);
                Bh[(vd + j) * S2 + vp] = hw;
                Bl[(vd + j) * S2 + vp] = lw;
            }
        }
        __syncthreads();
        mma_chunk2(Ah, Al, Bh, Bl, wm, wn, gid, tq, acc);
    }

    // epilogue: write split ctx words (adjacent cols 2tq, 2tq+1 -> one word)
#pragma unroll
    for (int mt = 0; mt < 4; mt++) {
        int row = q0 + wm + mt * 16 + gid;
#pragma unroll
        for (int nt = 0; nt < 4; nt++) {
            int colw = (h * 128 + wn + nt * 8 + 2 * tq) >> 1;
            uint32_t hw, lw;
            pack_split(acc[mt][nt][0], acc[mt][nt][1], hw, lw);
            size_t wi = ((size_t)b * SEQ + row) * WROW + colw;
            g_ch[wi] = hw;
            g_cl[wi] = lw;
            pack_split(acc[mt][nt][2], acc[mt][nt][3], hw, lw);
            size_t wi2 = ((size_t)b * SEQ + row + 8) * WROW + colw;
            g_ch[wi2] = hw;
            g_cl[wi2] = lw;
        }
    }
}

// ---------------------------------------------------------------------------
// RoPE fused with q/k split: reads float q/k, writes split word streams.
// Thread handles adjacent pair (d2, d2+1) and its partner (d2+64, d2+65).
// ---------------------------------------------------------------------------
__global__ void rope_split() {
    int idx = blockIdx.x * blockDim.x + threadIdx.x;
    if (idx >= MTOT * HEADS * 32) return;
    int p = idx & 31;                  // word index within half-head
    int h = (idx >> 5) & 15;
    int row = idx >> 9;
    int s = row & (SEQ - 1);
    int d2 = 2 * p;

    double i0 = pow(10000.0, -(double)d2 / 64.0);
    double i1 = pow(10000.0, -(double)(d2 + 1) / 64.0);
    float c0 = (float)cos((double)s * i0), s0 = (float)sin((double)s * i0);
    float c1 = (float)cos((double)s * i1), s1 = (float)sin((double)s * i1);

    size_t base = (size_t)row * HIDDEN + h * HEAD_DIM;
    size_t wbase = (size_t)row * WROW + h * 64;
    uint32_t hw, lw;

    {
        float a = g_q[base + d2], bq = g_q[base + d2 + 1];
        float c = g_q[base + d2 + 64], dq = g_q[base + d2 + 65];
        pack_split(a * c0 - c * s0, bq * c1 - dq * s1, hw, lw);
        g_qh[wbase + p] = hw; g_ql[wbase + p] = lw;
        pack_split(c * c0 + a * s0, dq * c1 + bq * s1, hw, lw);
        g_qh[wbase + 32 + p] = hw; g_ql[wbase + 32 + p] = lw;
    }
    {
        float a = g_k[base + d2], bk = g_k[base + d2 + 1];
        float c = g_k[base + d2 + 64], dk = g_k[base + d2 + 65];
        pack_split(a * c0 - c * s0, bk * c1 - dk * s1, hw, lw);
        g_kh[wbase + p] = hw; g_kl[wbase + p] = lw;
        pack_split(c * c0 + a * s0, dk * c1 + bk * s1, hw, lw);
        g_kh[wbase + 32 + p] = hw; g_kl[wbase + 32 + p] = lw;
    }
}

// ---------------------------------------------------------------------------
// Softmax per row; writes split P words (masked lanes zero, upper tri zero).
// ---------------------------------------------------------------------------
__global__ __launch_bounds__(256)
void softmax_split() {
    const int row = blockIdx.x;
    const int q = row & (SEQ - 1);
    const int bh = row >> 11;
    const float* S = g_sc + (size_t)bh * SEQ * SEQ + (size_t)q * SEQ;
    uint32_t* Ph = g_ph + (size_t)bh * SEQ * (SEQ / 2) + (size_t)q * (SEQ / 2);
    uint32_t* Pl = g_pl + (size_t)bh * SEQ * (SEQ / 2) + (size_t)q * (SEQ / 2);
    const int n = q + 1;
    const int tid = threadIdx.x;
    __shared__ float red[256];

    float mx = -1e30f;
    for (int j = tid; j < n; j += 256) mx = fmaxf(mx, S[j]);
    red[tid] = mx;
    __syncthreads();
    for (int s = 128; s > 0; s >>= 1) {
        if (tid < s) red[tid] = fmaxf(red[tid], red[tid + s]);
        __syncthreads();
    }
    float m = red[0];
    __syncthreads();

    float sum = 0.f;
    for (int j = tid; j < n; j += 256) sum += __expf(S[j] - m);
    red[tid] = sum;
    __syncthreads();
    for (int s = 128; s > 0; s >>= 1) {
        if (tid < s) red[tid] += red[tid + s];
        __syncthreads();
    }
    float inv = 1.0f / red[0];

    for (int j2 = tid; j2 < SEQ / 2; j2 += 256) {
        int j = 2 * j2;
        float p0 = (j < n) ? __expf(S[j] - m) * inv : 0.f;
        float p1 = (j + 1 < n) ? __expf(S[j + 1] - m) * inv : 0.f;
        uint32_t hw, lw;
        pack_split(p0, p1, hw, lw);
        Ph[j2] = hw;
        Pl[j2] = lw;
    }
}

// ---------------------------------------------------------------------------
extern "C" void kernel_launch(void* const* d_in, const int* in_sizes, int n_in,
                              void* d_out, int out_size) {
    int xi = 0;
    for (int i = 0; i < n_in; i++)
        if (in_sizes[i] == MTOT * HIDDEN) { xi = i; break; }

    const float* x;
    const float *Wq, *Wk, *Wv, *Wo;
    if (xi == 0) {
        x  = (const float*)d_in[0];
        Wq = (const float*)d_in[1];
        Wk = (const float*)d_in[2];
        Wv = (const float*)d_in[3];
        Wo = (const float*)d_in[4];
    } else {
        const float* w[4]; int j = 0;
        for (int i = 0; i < n_in; i++)
            if (i != xi) w[j++] = (const float*)d_in[i];
        x = (const float*)d_in[xi];
        Wk = w[0]; Wo = w[1]; Wq = w[2]; Wv = w[3];
    }

    float *qp, *kp, *vp;
    uint32_t *xh, *xl, *wh, *wl, *ch, *cl;
    cudaGetSymbolAddress((void**)&qp, g_q);
    cudaGetSymbolAddress((void**)&kp, g_k);
    cudaGetSymbolAddress((void**)&vp, g_v);
    cudaGetSymbolAddress((void**)&xh, g_xh);
    cudaGetSymbolAddress((void**)&xl, g_xl);
    cudaGetSymbolAddress((void**)&wh, g_wh);
    cudaGetSymbolAddress((void**)&wl, g_wl);
    cudaGetSymbolAddress((void**)&ch, g_ch);
    cudaGetSymbolAddress((void**)&cl, g_cl);

    cudaFuncSetAttribute(gemm_ps,
                         cudaFuncAttributeMaxDynamicSharedMemorySize, SMEM2);
    cudaFuncSetAttribute(scores_ps,
                         cudaFuncAttributeMaxDynamicSharedMemorySize, SMEM2);
    cudaFuncSetAttribute(pv_ps,
                         cudaFuncAttributeMaxDynamicSharedMemorySize, SMEM2);

    const int XW4 = MTOT * WROW / 4;      // x words / 4
    const int WW4 = HIDDEN * WROW / 4;    // weight words / 4
    const int WN = HIDDEN * WROW;

    split_pair<<<XW4 / 256, 256>>>(x, xh, xl, XW4);
    split_pair<<<WW4 / 256, 256>>>(Wq, wh + 0 * WN, wl + 0 * WN, WW4);
    split_pair<<<WW4 / 256, 256>>>(Wk, wh + 1 * WN, wl + 1 * WN, WW4);
    split_pair<<<WW4 / 256, 256>>>(Wv, wh + 2 * WN, wl + 2 * WN, WW4);
    split_pair<<<WW4 / 256, 256>>>(Wo, wh + 3 * WN, wl + 3 * WN, WW4);

    dim3 gg(HIDDEN / 128, MTOT / 128);   // (16, 32)
    gemm_ps<<<gg, 256, SMEM2>>>(xh, xl, wh + 0 * WN, wl + 0 * WN, qp);
    gemm_ps<<<gg, 256, SMEM2>>>(xh, xl, wh + 1 * WN, wl + 1 * WN, kp);
    gemm_ps<<<gg, 256, SMEM2>>>(xh, xl, wh + 2 * WN, wl + 2 * WN, vp);

    rope_split<<<(MTOT * HEADS * 32 + 255) / 256, 256>>>();

    scores_ps<<<dim3(SEQ / 128, SEQ / 128, BH), 256, SMEM2>>>();
    softmax_split<<<BH * SEQ, 256>>>();
    pv_ps<<<dim3(SEQ / 128, BH), 256, SMEM2>>>();

    gemm_ps<<<gg, 256, SMEM2>>>(ch, cl, wh + 3 * WN, wl + 3 * WN, (float*)d_out);
}

// round 17
// speedup vs baseline: 1.0956x; 1.0956x over previous
#include <cuda_runtime.h>
#include <cuda_bf16.h>
#include <math.h>
#include <stdint.h>

#define HIDDEN 2048
#define HEADS 16
#define HEAD_DIM 128
#define BATCH 2
#define SEQ 2048
#define MTOT (BATCH * SEQ)     // 4096
#define BH (BATCH * HEADS)     // 32

// ---------------- scratch (device globals; no allocations allowed) ----------
__device__ float g_q[MTOT * HIDDEN];
__device__ float g_k[MTOT * HIDDEN];
__device__ float g_v[MTOT * HIDDEN];
__device__ float g_ctx[MTOT * HIDDEN];

// ---------------------------------------------------------------------------
__device__ __forceinline__ void pack_split(float v0, float v1,
                                           uint32_t& hi, uint32_t& lo) {
    __nv_bfloat162 h = __floats2bfloat162_rn(v0, v1);
    float2 hf = __bfloat1622float2(h);
    __nv_bfloat162 l = __floats2bfloat162_rn(v0 - hf.x, v1 - hf.y);
    hi = *reinterpret_cast<uint32_t*>(&h);
    lo = *reinterpret_cast<uint32_t*>(&l);
}

__device__ __forceinline__ void mma_bf16(float* c, const uint32_t* a, const uint32_t* b) {
    asm("mma.sync.aligned.m16n8k16.row.col.f32.bf16.bf16.f32 "
        "{%0,%1,%2,%3}, {%4,%5,%6,%7}, {%8,%9}, {%0,%1,%2,%3};"
        : "+f"(c[0]), "+f"(c[1]), "+f"(c[2]), "+f"(c[3])
        : "r"(a[0]), "r"(a[1]), "r"(a[2]), "r"(a[3]), "r"(b[0]), "r"(b[1]));
}

// ======================= R11 proven projection GEMM =========================
#define KC 32
#define S2 20
#define TILE2 (128 * S2)
#define SMEM2 (4 * TILE2 * 4)

__device__ __forceinline__ void mma_chunk2(
    const uint32_t* Ah, const uint32_t* Al, const uint32_t* Bh, const uint32_t* Bl,
    int wm, int wn, int gid, int tq, float acc[4][4][4]) {
#pragma unroll
    for (int ks = 0; ks < 2; ks++) {
        const int kb = ks * 8;
        uint32_t bh[4][2], bl[4][2];
#pragma unroll
        for (int nt = 0; nt < 4; nt++) {
            int nr = (wn + nt * 8 + gid) * S2 + kb + tq;
            bh[nt][0] = Bh[nr];
            bh[nt][1] = Bh[nr + 4];
            bl[nt][0] = Bl[nr];
            bl[nt][1] = Bl[nr + 4];
        }
        uint32_t af[4][4];
#pragma unroll
        for (int mt = 0; mt < 4; mt++) {
            int r = (wm + mt * 16 + gid) * S2 + kb + tq;
            af[mt][0] = Ah[r];
            af[mt][1] = Ah[r + 8 * S2];
            af[mt][2] = Ah[r + 4];
            af[mt][3] = Ah[r + 8 * S2 + 4];
        }
#pragma unroll
        for (int mt = 0; mt < 4; mt++)
#pragma unroll
            for (int nt = 0; nt < 4; nt++) {
                mma_bf16(acc[mt][nt], af[mt], bh[nt]);
                mma_bf16(acc[mt][nt], af[mt], bl[nt]);
            }
#pragma unroll
        for (int mt = 0; mt < 4; mt++) {
            int r = (wm + mt * 16 + gid) * S2 + kb + tq;
            af[mt][0] = Al[r];
            af[mt][1] = Al[r + 8 * S2];
            af[mt][2] = Al[r + 4];
            af[mt][3] = Al[r + 8 * S2 + 4];
        }
#pragma unroll
        for (int mt = 0; mt < 4; mt++)
#pragma unroll
            for (int nt = 0; nt < 4; nt++)
                mma_bf16(acc[mt][nt], af[mt], bh[nt]);
    }
}

__device__ __forceinline__ void stage16(const float4* v, uint32_t* Hi, uint32_t* Lo,
                                        int base) {
#pragma unroll
    for (int i = 0; i < 4; i++) {
        uint32_t h0, l0, h1, l1;
        pack_split(v[i].x, v[i].y, h0, l0);
        pack_split(v[i].z, v[i].w, h1, l1);
        Hi[base + 2 * i]     = h0;
        Lo[base + 2 * i]     = l0;
        Hi[base + 2 * i + 1] = h1;
        Lo[base + 2 * i + 1] = l1;
    }
}

__global__ __launch_bounds__(256, 2)
void gemm_bf16(const float* __restrict__ A, const float* __restrict__ W,
               float* __restrict__ C) {
    extern __shared__ __align__(16) uint32_t sm[];
    uint32_t* Ah = sm;
    uint32_t* Al = Ah + TILE2;
    uint32_t* Bh = Al + TILE2;
    uint32_t* Bl = Bh + TILE2;

    const int tid = threadIdx.x;
    const int warp = tid >> 5, lane = tid & 31;
    const int gid = lane >> 2, tq = lane & 3;
    const int wm = (warp & 1) * 64;
    const int wn = (warp >> 1) * 32;
    const int m0 = blockIdx.y * 128, n0 = blockIdx.x * 128;
    const int lr = tid >> 1;
    const int lc = (tid & 1) * 16;
    const int wb = (tid & 1) * 8;

    float acc[4][4][4];
#pragma unroll
    for (int mt = 0; mt < 4; mt++)
#pragma unroll
        for (int nt = 0; nt < 4; nt++)
#pragma unroll
            for (int r = 0; r < 4; r++) acc[mt][nt][r] = 0.f;

    const float* Ap = A + (size_t)(m0 + lr) * HIDDEN + lc;
    const float* Wp = W + (size_t)(n0 + lr) * HIDDEN + lc;

    for (int kt = 0; kt < HIDDEN; kt += KC) {
        float4 av[4], wv[4];
#pragma unroll
        for (int i = 0; i < 4; i++) {
            av[i] = *(const float4*)(Ap + kt + 4 * i);
            wv[i] = *(const float4*)(Wp + kt + 4 * i);
        }
        __syncthreads();
        stage16(av, Ah, Al, lr * S2 + wb);
        stage16(wv, Bh, Bl, lr * S2 + wb);
        __syncthreads();
        mma_chunk2(Ah, Al, Bh, Bl, wm, wn, gid, tq, acc);
    }

#pragma unroll
    for (int mt = 0; mt < 4; mt++) {
        int row = m0 + wm + mt * 16 + gid;
#pragma unroll
        for (int nt = 0; nt < 4; nt++) {
            int col = n0 + wn + nt * 8 + 2 * tq;
            *(float2*)&C[(size_t)row * HIDDEN + col] =
                make_float2(acc[mt][nt][0], acc[mt][nt][1]);
            *(float2*)&C[(size_t)(row + 8) * HIDDEN + col] =
                make_float2(acc[mt][nt][2], acc[mt][nt][3]);
        }
    }
}

// ======================= fused flash attention ==============================
// Block: 256 threads (8 warps), q-tile 128 (warp w -> rows q0+16w..+15),
// kv-tiles of 64. Q/K staged split-bf16 (dpair words, stride 68); V staged
// kv-pair-packed transposed (stride 36). Online softmax; P reused from S-acc
// registers as A fragments (layout identity). O unnormalized until the end.
#define QSTRIDE 68
#define VSTRIDE 36
#define FQH 0
#define FQL (FQH + 128 * QSTRIDE)        // 8704
#define FKH (FQL + 128 * QSTRIDE)        // 17408
#define FKL (FKH + 64 * QSTRIDE)         // 21760
#define FVH (FKL + 64 * QSTRIDE)         // 26112
#define FVL (FVH + 128 * VSTRIDE)        // 30720
#define FSMEM ((FVL + 128 * VSTRIDE) * 4)  // 141312 bytes

__global__ __launch_bounds__(256)
void flash_attn() {
    extern __shared__ __align__(16) uint32_t fsm[];
    uint32_t* QH = fsm + FQH;
    uint32_t* QL = fsm + FQL;
    uint32_t* KH = fsm + FKH;
    uint32_t* KL = fsm + FKL;
    uint32_t* VH = fsm + FVH;
    uint32_t* VL = fsm + FVL;

    const int tid = threadIdx.x;
    const int warp = tid >> 5, lane = tid & 31;
    const int gid = lane >> 2, tq = lane & 3;
    const int q0 = blockIdx.x * 128;
    const int bh = blockIdx.y;
    const int b = bh >> 4, h = bh & 15;

    const float* Q = g_q + (size_t)b * SEQ * HIDDEN + h * HEAD_DIM;
    const float* K = g_k + (size_t)b * SEQ * HIDDEN + h * HEAD_DIM;
    const float* V = g_v + (size_t)b * SEQ * HIDDEN + h * HEAD_DIM;

    // ---- stage Q tile once: 128 rows x 64 dpairs ----
    {
        const int row = tid >> 1, ds = (tid & 1) * 32;   // dpair base 0/32
        const float* src = Q + (size_t)(q0 + row) * HIDDEN + ds * 2;
#pragma unroll
        for (int j = 0; j < 16; j++) {
            float4 f = ((const float4*)src)[j];
            uint32_t h0, l0, h1, l1;
            pack_split(f.x, f.y, h0, l0);
            pack_split(f.z, f.w, h1, l1);
            int o = row * QSTRIDE + ds + 2 * j;
            QH[o] = h0; QL[o] = l0;
            QH[o + 1] = h1; QL[o + 1] = l1;
        }
    }

    float accO[16][4];
#pragma unroll
    for (int nt = 0; nt < 16; nt++)
#pragma unroll
        for (int c = 0; c < 4; c++) accO[nt][c] = 0.f;
    float m0r = -1e30f, m1r = -1e30f, l0r = 0.f, l1r = 0.f;

    const float sm_scale = 0.08838834764831845f;  // 1/sqrt(128)
    const int row0 = q0 + warp * 16 + gid;
    const int ntiles = q0 / 64 + 2;

    for (int t = 0; t < ntiles; t++) {
        const int kv0 = t * 64;
        __syncthreads();
        // stage K: 64 rows x 64 dpairs
        {
            const int row = tid >> 2, ds = (tid & 3) * 16;
            const float* src = K + (size_t)(kv0 + row) * HIDDEN + ds * 2;
#pragma unroll
            for (int j = 0; j < 8; j++) {
                float4 f = ((const float4*)src)[j];
                uint32_t h0, l0, h1, l1;
                pack_split(f.x, f.y, h0, l0);
                pack_split(f.z, f.w, h1, l1);
                int o = row * QSTRIDE + ds + 2 * j;
                KH[o] = h0; KL[o] = l0;
                KH[o + 1] = h1; KL[o + 1] = l1;
            }
        }
        // stage V transposed kv-pair-packed: word(d, p) = pack(V[2p][d], V[2p+1][d])
        {
            const int p = tid & 31, dsg = (tid >> 5) * 16;
            const float* v0 = V + (size_t)(kv0 + 2 * p) * HIDDEN + dsg;
            const float* v1 = v0 + HIDDEN;
#pragma unroll
            for (int j = 0; j < 4; j++) {
                float4 a = ((const float4*)v0)[j];
                float4 c = ((const float4*)v1)[j];
                float a4[4] = {a.x, a.y, a.z, a.w};
                float c4[4] = {c.x, c.y, c.z, c.w};
#pragma unroll
                for (int e = 0; e < 4; e++) {
                    uint32_t hw, lw;
                    pack_split(a4[e], c4[e], hw, lw);
                    VH[(dsg + 4 * j + e) * VSTRIDE + p] = hw;
                    VL[(dsg + 4 * j + e) * VSTRIDE + p] = lw;
                }
            }
        }
        __syncthreads();

        // ---- S = Q . K^T (16 q rows x 64 kv cols per warp) ----
        float accS[8][4];
#pragma unroll
        for (int nt = 0; nt < 8; nt++)
#pragma unroll
            for (int c = 0; c < 4; c++) accS[nt][c] = 0.f;

#pragma unroll
        for (int kc = 0; kc < 8; kc++) {
            uint32_t aH[4], aL[4];
            const int qr = (warp * 16 + gid) * QSTRIDE + kc * 8 + tq;
            aH[0] = QH[qr];
            aH[1] = QH[qr + 8 * QSTRIDE];
            aH[2] = QH[qr + 4];
            aH[3] = QH[qr + 8 * QSTRIDE + 4];
            aL[0] = QL[qr];
            aL[1] = QL[qr + 8 * QSTRIDE];
            aL[2] = QL[qr + 4];
            aL[3] = QL[qr + 8 * QSTRIDE + 4];
#pragma unroll
            for (int nt = 0; nt < 8; nt++) {
                const int kr = (nt * 8 + gid) * QSTRIDE + kc * 8 + tq;
                uint32_t bH[2] = {KH[kr], KH[kr + 4]};
                uint32_t bL[2] = {KL[kr], KL[kr + 4]};
                mma_bf16(accS[nt], aH, bH);
                mma_bf16(accS[nt], aH, bL);
                mma_bf16(accS[nt], aL, bH);
            }
        }

        // scale + causal mask
#pragma unroll
        for (int nt = 0; nt < 8; nt++)
#pragma unroll
            for (int c = 0; c < 4; c++) accS[nt][c] *= sm_scale;
        if (kv0 + 63 > row0) {
#pragma unroll
            for (int nt = 0; nt < 8; nt++) {
                int col = kv0 + nt * 8 + 2 * tq;
                if (col > row0)     accS[nt][0] = -1e30f;
                if (col + 1 > row0) accS[nt][1] = -1e30f;
                if (col > row0 + 8)     accS[nt][2] = -1e30f;
                if (col + 1 > row0 + 8) accS[nt][3] = -1e30f;
            }
        }

        // online softmax (rows row0 -> c0,c1 ; row0+8 -> c2,c3)
        float mx0 = -1e30f, mx1 = -1e30f;
#pragma unroll
        for (int nt = 0; nt < 8; nt++) {
            mx0 = fmaxf(mx0, fmaxf(accS[nt][0], accS[nt][1]));
            mx1 = fmaxf(mx1, fmaxf(accS[nt][2], accS[nt][3]));
        }
        mx0 = fmaxf(mx0, __shfl_xor_sync(0xFFFFFFFFu, mx0, 1));
        mx0 = fmaxf(mx0, __shfl_xor_sync(0xFFFFFFFFu, mx0, 2));
        mx1 = fmaxf(mx1, __shfl_xor_sync(0xFFFFFFFFu, mx1, 1));
        mx1 = fmaxf(mx1, __shfl_xor_sync(0xFFFFFFFFu, mx1, 2));
        const float mn0 = fmaxf(m0r, mx0);
        const float mn1 = fmaxf(m1r, mx1);
        const float corr0 = __expf(m0r - mn0);
        const float corr1 = __expf(m1r - mn1);
        m0r = mn0; m1r = mn1;

        float s0 = 0.f, s1 = 0.f;
#pragma unroll
        for (int nt = 0; nt < 8; nt++) {
            accS[nt][0] = __expf(accS[nt][0] - mn0);
            accS[nt][1] = __expf(accS[nt][1] - mn0);
            accS[nt][2] = __expf(accS[nt][2] - mn1);
            accS[nt][3] = __expf(accS[nt][3] - mn1);
            s0 += accS[nt][0] + accS[nt][1];
            s1 += accS[nt][2] + accS[nt][3];
        }
        s0 += __shfl_xor_sync(0xFFFFFFFFu, s0, 1);
        s0 += __shfl_xor_sync(0xFFFFFFFFu, s0, 2);
        s1 += __shfl_xor_sync(0xFFFFFFFFu, s1, 1);
        s1 += __shfl_xor_sync(0xFFFFFFFFu, s1, 2);
        l0r = l0r * corr0 + s0;
        l1r = l1r * corr1 + s1;

#pragma unroll
        for (int nt = 0; nt < 16; nt++) {
            accO[nt][0] *= corr0;
            accO[nt][1] *= corr0;
            accO[nt][2] *= corr1;
            accO[nt][3] *= corr1;
        }

        // ---- O += P . V  (P fragments straight from accS) ----
#pragma unroll
        for (int kc = 0; kc < 4; kc++) {
            uint32_t pH[4], pL[4];
            pack_split(accS[2 * kc][0], accS[2 * kc][1], pH[0], pL[0]);
            pack_split(accS[2 * kc][2], accS[2 * kc][3], pH[1], pL[1]);
            pack_split(accS[2 * kc + 1][0], accS[2 * kc + 1][1], pH[2], pL[2]);
            pack_split(accS[2 * kc + 1][2], accS[2 * kc + 1][3], pH[3], pL[3]);
#pragma unroll
            for (int ntd = 0; ntd < 16; ntd++) {
                const int vr = (ntd * 8 + gid) * VSTRIDE + kc * 8 + tq;
                uint32_t bH[2] = {VH[vr], VH[vr + 4]};
                uint32_t bL[2] = {VL[vr], VL[vr + 4]};
                mma_bf16(accO[ntd], pH, bH);
                mma_bf16(accO[ntd], pH, bL);
                mma_bf16(accO[ntd], pL, bH);
            }
        }
    }

    // finalize
    const float inv0 = 1.0f / l0r;
    const float inv1 = 1.0f / l1r;
    float* O = g_ctx + ((size_t)b * SEQ + row0) * HIDDEN + h * HEAD_DIM;
#pragma unroll
    for (int ntd = 0; ntd < 16; ntd++) {
        int col = ntd * 8 + 2 * tq;
        *(float2*)&O[col] = make_float2(accO[ntd][0] * inv0, accO[ntd][1] * inv0);
        *(float2*)&O[(size_t)8 * HIDDEN + col] =
            make_float2(accO[ntd][2] * inv1, accO[ntd][3] * inv1);
    }
}

// ---------------------------------------------------------------------------
// RoPE (proven).
// ---------------------------------------------------------------------------
__global__ void rope2() {
    int idx = blockIdx.x * blockDim.x + threadIdx.x;
    if (idx >= MTOT * 1024) return;
    int d = idx & 63;
    int h = (idx >> 6) & 15;
    int row = idx >> 10;
    int s = row & (SEQ - 1);

    double inv = pow(10000.0, -((double)d) / 64.0);
    double ang = (double)s * inv;
    float c = (float)cos(ang);
    float sn = (float)sin(ang);

    size_t i1 = (size_t)row * HIDDEN + h * HEAD_DIM + d;
    float q1 = g_q[i1], q2 = g_q[i1 + 64];
    g_q[i1]      = q1 * c - q2 * sn;
    g_q[i1 + 64] = q2 * c + q1 * sn;
    float k1 = g_k[i1], k2 = g_k[i1 + 64];
    g_k[i1]      = k1 * c - k2 * sn;
    g_k[i1 + 64] = k2 * c + k1 * sn;
}

// ---------------------------------------------------------------------------
extern "C" void kernel_launch(void* const* d_in, const int* in_sizes, int n_in,
                              void* d_out, int out_size) {
    int xi = 0;
    for (int i = 0; i < n_in; i++)
        if (in_sizes[i] == MTOT * HIDDEN) { xi = i; break; }

    const float* x;
    const float *Wq, *Wk, *Wv, *Wo;
    if (xi == 0) {
        x  = (const float*)d_in[0];
        Wq = (const float*)d_in[1];
        Wk = (const float*)d_in[2];
        Wv = (const float*)d_in[3];
        Wo = (const float*)d_in[4];
    } else {
        const float* w[4]; int j = 0;
        for (int i = 0; i < n_in; i++)
            if (i != xi) w[j++] = (const float*)d_in[i];
        x = (const float*)d_in[xi];
        Wk = w[0]; Wo = w[1]; Wq = w[2]; Wv = w[3];
    }

    float *qp, *kp, *vp, *cp;
    cudaGetSymbolAddress((void**)&qp, g_q);
    cudaGetSymbolAddress((void**)&kp, g_k);
    cudaGetSymbolAddress((void**)&vp, g_v);
    cudaGetSymbolAddress((void**)&cp, g_ctx);

    cudaFuncSetAttribute(gemm_bf16,
                         cudaFuncAttributeMaxDynamicSharedMemorySize, SMEM2);
    cudaFuncSetAttribute(flash_attn,
                         cudaFuncAttributeMaxDynamicSharedMemorySize, FSMEM);

    dim3 gg(HIDDEN / 128, MTOT / 128);   // (16, 32)
    gemm_bf16<<<gg, 256, SMEM2>>>(x, Wq, qp);
    gemm_bf16<<<gg, 256, SMEM2>>>(x, Wk, kp);
    gemm_bf16<<<gg, 256, SMEM2>>>(x, Wv, vp);

    rope2<<<(MTOT * 1024 + 255) / 256, 256>>>();

    flash_attn<<<dim3(SEQ / 128, BH), 256, FSMEM>>>();

    gemm_bf16<<<gg, 256, SMEM2>>>(cp, Wo, (float*)d_out);
}